// round 5
// baseline (speedup 1.0000x reference)
#include <cuda_runtime.h>
#include <cuda_fp16.h>

#define D 64
#define NT_MAX 300000
#define NU_MAX 300000
#define ND_MAX 100000
#define E_MAX  2000000
#define SCAN_B 1024
#define MAX_SCAN_BLOCKS 512

// ---------------- scratch (static __device__, no allocation) ----------------
__device__ __half2 g_feat_h[(size_t)NT_MAX * D / 2];  // fp16 copy of features
__device__ float2 g_z_u[NU_MAX];               // lrelu(mf_u@W0[1]+b0[1]) @ (W1[0]@Wc)
__device__ float2 g_z_d[ND_MAX];
__device__ float2 g_acc_t1[NT_MAX];            // scatter sums of z_u over u2t
__device__ float2 g_acc_t2[NT_MAX];            // scatter sums of z_d over d2t

__device__ int g_eidx_t2u[E_MAX];
__device__ int g_eidx_t2d[E_MAX];

__device__ int g_cnt_u[NU_MAX],  g_off_u[NU_MAX],  g_cur_u[NU_MAX];
__device__ int g_cnt_d[ND_MAX],  g_off_d[ND_MAX],  g_cur_d[ND_MAX];
__device__ int g_cnt_t1[NT_MAX];
__device__ int g_cnt_t2[NT_MAX];
__device__ int g_bsum[MAX_SCAN_BLOCKS];
__device__ float g_Wf[2 * D * 2];              // folded W1@Wc for u (idx 0) and d (idx 1)
__device__ float g_cvec[4];                    // cU0,cU1,cD0,cD1 = b1@Wc constants

// ---------------- kernels ----------------

// features (fp32) -> fp16 table
__global__ __launch_bounds__(256) void convert_half_k(const float* __restrict__ F,
                                                      __half2* __restrict__ H, int n2)
{
    for (int i = blockIdx.x * blockDim.x + threadIdx.x; i < n2;
         i += gridDim.x * blockDim.x) {
        float2 v = __ldg(reinterpret_cast<const float2*>(F) + i);
        H[i] = __floats2half2_rn(v.x, v.y);
    }
}

// Fold classifier into layer-1 weights:
//   Wf[r][k][j] = sum_h W1[sel_r][k][h] * Wc[h][j],  sel = {0 (u2t), 2 (d2t)}
//   cvec[r*2+j] = sum_h b1[sel_r][h] * Wc[h][j]
__global__ void prep_k(const float* __restrict__ W1, const float* __restrict__ b1,
                       const float* __restrict__ Wc,
                       float* __restrict__ Wf, float* __restrict__ cvec)
{
    int tid = threadIdx.x;               // 256 threads: r(1b) k(6b) j(1b)
    int r = tid >> 7;
    int k = (tid >> 1) & 63;
    int j = tid & 1;
    int sel = (r == 0) ? 0 : 2;
    const float* w = W1 + (size_t)sel * D * D + (size_t)k * D;
    float acc = 0.f;
#pragma unroll
    for (int h = 0; h < D; ++h) acc += w[h] * Wc[h * 2 + j];
    Wf[r * D * 2 + k * 2 + j] = acc;
    if (tid < 4) {
        int rr = tid >> 1, jj = tid & 1;
        int ss = (rr == 0) ? 0 : 2;
        float c = 0.f;
        const float* bb = b1 + (size_t)ss * D;
#pragma unroll
        for (int h = 0; h < D; ++h) c += bb[h] * Wc[h * 2 + jj];
        cvec[rr * 2 + jj] = c;
    }
}

// in-degree histogram (grid-stride)
__global__ __launch_bounds__(256) void count_k(const int* __restrict__ dst,
                                               int* __restrict__ cnt, int e)
{
    for (int i = blockIdx.x * blockDim.x + threadIdx.x; i < e;
         i += gridDim.x * blockDim.x)
        atomicAdd(&cnt[dst[i]], 1);
}

// block-level exclusive scan
__global__ __launch_bounds__(SCAN_B) void scan_blocks_k(const int* __restrict__ cnt,
                                                        int* __restrict__ off,
                                                        int* __restrict__ bsum, int n)
{
    __shared__ int sh[SCAN_B];
    int tid = threadIdx.x;
    int i = blockIdx.x * SCAN_B + tid;
    int v = (i < n) ? cnt[i] : 0;
    sh[tid] = v;
    __syncthreads();
    for (int o = 1; o < SCAN_B; o <<= 1) {
        int t = (tid >= o) ? sh[tid - o] : 0;
        __syncthreads();
        sh[tid] += t;
        __syncthreads();
    }
    if (i < n) off[i] = sh[tid] - v;
    if (tid == SCAN_B - 1) bsum[blockIdx.x] = sh[tid];
}

__global__ __launch_bounds__(SCAN_B) void scan_sums_k(int* bsum, int nb)
{
    __shared__ int sh[SCAN_B];
    int tid = threadIdx.x;
    int v = (tid < nb) ? bsum[tid] : 0;
    sh[tid] = v;
    __syncthreads();
    for (int o = 1; o < SCAN_B; o <<= 1) {
        int t = (tid >= o) ? sh[tid - o] : 0;
        __syncthreads();
        sh[tid] += t;
        __syncthreads();
    }
    if (tid < nb) bsum[tid] = sh[tid] - v;
}

__global__ __launch_bounds__(SCAN_B) void scan_add_k(int* off, const int* __restrict__ bsum, int n)
{
    int i = blockIdx.x * SCAN_B + threadIdx.x;
    if (i < n) off[i] += bsum[blockIdx.x];
}

// place each edge's src into its destination's CSR slot (grid-stride)
__global__ __launch_bounds__(256) void fill_k(const int* __restrict__ src,
                                              const int* __restrict__ dst,
                                              const int* __restrict__ off,
                                              int* __restrict__ cur,
                                              int* __restrict__ eidx, int e)
{
    for (int i = blockIdx.x * blockDim.x + threadIdx.x; i < e;
         i += gridDim.x * blockDim.x) {
        int d = dst[i];
        int p = atomicAdd(&cur[d], 1);
        eidx[off[d] + p] = src[i];
    }
}

__device__ __forceinline__ float lrelu(float x) { return x > 0.0f ? x : 0.01f * x; }

// Fully fused per-node pipeline (16 lanes/row, 16 rows/block):
//   mf   = mean of fp16 FEAT[src] over in-edges       (gather, fp32 accum)
//   z    = lrelu(mf @ W + b*(deg>0)) @ [Wf0|Wf1]      (proj through smem)
__global__ __launch_bounds__(256) void gather_proj_k(const float2* __restrict__ FEATH, // half2x2 view
                                                     const int* __restrict__ off,
                                                     const int* __restrict__ cnt,
                                                     const int* __restrict__ eidx,
                                                     const float* __restrict__ W,   // 64x64
                                                     const float* __restrict__ B,   // 64
                                                     const float* __restrict__ Wf,  // 64x2
                                                     float2* __restrict__ Z, int n)
{
    __shared__ float Wsh[D * D];       // 16 KB
    __shared__ float Bsh[D];
    __shared__ float Wf0[D], Wf1[D];
    __shared__ float mf[16][D + 4];    // +4 pad vs bank conflicts

    for (int i = threadIdx.x; i < D * D; i += 256) Wsh[i] = W[i];
    if (threadIdx.x < D) {
        Bsh[threadIdx.x] = B[threadIdx.x];
        Wf0[threadIdx.x] = Wf[threadIdx.x * 2 + 0];
        Wf1[threadIdx.x] = Wf[threadIdx.x * 2 + 1];
    }
    __syncthreads();

    int idx  = blockIdx.x * 256 + threadIdx.x;
    int row  = idx >> 4;
    int lane = idx & 15;
    int lrow = threadIdx.x >> 4;
    bool active = row < n;

    int beg = 0, deg = 0;
    if (active) {
        beg = __ldg(&off[row]);
        deg = __ldg(&cnt[row]);
    }

    // gather: lane holds dims [4*lane .. 4*lane+3]; 8 B fp16 load per edge
    float a0 = 0.f, a1 = 0.f, a2 = 0.f, a3 = 0.f;
    int i = 0;
    for (; i + 2 <= deg; i += 2) {
        int s0 = __ldg(&eidx[beg + i]);
        int s1 = __ldg(&eidx[beg + i + 1]);
        float2 r0 = __ldg(FEATH + (size_t)s0 * 16 + lane);
        float2 r1 = __ldg(FEATH + (size_t)s1 * 16 + lane);
        float2 p00 = __half22float2(*reinterpret_cast<__half2*>(&r0.x));
        float2 p01 = __half22float2(*reinterpret_cast<__half2*>(&r0.y));
        float2 p10 = __half22float2(*reinterpret_cast<__half2*>(&r1.x));
        float2 p11 = __half22float2(*reinterpret_cast<__half2*>(&r1.y));
        a0 += p00.x + p10.x; a1 += p00.y + p10.y;
        a2 += p01.x + p11.x; a3 += p01.y + p11.y;
    }
    if (i < deg) {
        int s0 = __ldg(&eidx[beg + i]);
        float2 r0 = __ldg(FEATH + (size_t)s0 * 16 + lane);
        float2 p00 = __half22float2(*reinterpret_cast<__half2*>(&r0.x));
        float2 p01 = __half22float2(*reinterpret_cast<__half2*>(&r0.y));
        a0 += p00.x; a1 += p00.y; a2 += p01.x; a3 += p01.y;
    }
    float inv = 1.0f / (float)(deg > 0 ? deg : 1);
    mf[lrow][lane * 4 + 0] = a0 * inv;
    mf[lrow][lane * 4 + 1] = a1 * inv;
    mf[lrow][lane * 4 + 2] = a2 * inv;
    mf[lrow][lane * 4 + 3] = a3 * inv;
    __syncthreads();

    // projection: lane computes output columns [4*lane .. 4*lane+3]
    float bias = (deg > 0) ? 1.0f : 0.0f;
    float4 acc;
    acc.x = bias * Bsh[lane * 4 + 0];
    acc.y = bias * Bsh[lane * 4 + 1];
    acc.z = bias * Bsh[lane * 4 + 2];
    acc.w = bias * Bsh[lane * 4 + 3];
#pragma unroll 8
    for (int k = 0; k < D; ++k) {
        float xk = mf[lrow][k];
        const float4 wv = *reinterpret_cast<const float4*>(Wsh + k * D + lane * 4);
        acc.x += xk * wv.x;
        acc.y += xk * wv.y;
        acc.z += xk * wv.z;
        acc.w += xk * wv.w;
    }
    int c = lane * 4;
    float h0 = lrelu(acc.x), h1 = lrelu(acc.y), h2 = lrelu(acc.z), h3 = lrelu(acc.w);
    float s0 = h0 * Wf0[c] + h1 * Wf0[c + 1] + h2 * Wf0[c + 2] + h3 * Wf0[c + 3];
    float s1 = h0 * Wf1[c] + h1 * Wf1[c + 1] + h2 * Wf1[c + 2] + h3 * Wf1[c + 3];

#pragma unroll
    for (int o = 8; o > 0; o >>= 1) {
        s0 += __shfl_down_sync(0xffffffffu, s0, o, 16);
        s1 += __shfl_down_sync(0xffffffffu, s1, o, 16);
    }
    if (active && lane == 0) Z[row] = make_float2(s0, s1);
}

// per edge: ACC[dst] += Z[src]   (2-float payload, red.global v2)
__global__ __launch_bounds__(256) void scatter2_k(const float2* __restrict__ Z,
                                                  const int* __restrict__ src,
                                                  const int* __restrict__ dst,
                                                  float2* __restrict__ ACC, int e)
{
    for (int i = blockIdx.x * blockDim.x + threadIdx.x; i < e;
         i += gridDim.x * blockDim.x) {
        int sidx = __ldg(&src[i]);
        int didx = __ldg(&dst[i]);
        float2 v = __ldg(&Z[sidx]);
        float* q = reinterpret_cast<float*>(ACC + didx);
        asm volatile("red.global.add.v2.f32 [%0], {%1, %2};"
                     :: "l"(q), "f"(v.x), "f"(v.y) : "memory");
    }
}

// out[t] = acc1*inv1 + cU*(deg1>0) + acc2*inv2 + cD*(deg2>0) + bc
__global__ __launch_bounds__(256) void combine_k(const float2* __restrict__ A1,
                                                 const float2* __restrict__ A2,
                                                 const int* __restrict__ c1,
                                                 const int* __restrict__ c2,
                                                 const float* __restrict__ cvec,
                                                 const float* __restrict__ bc,
                                                 float2* __restrict__ out, int n)
{
    int i = blockIdx.x * 256 + threadIdx.x;
    if (i >= n) return;
    int d1 = __ldg(&c1[i]);
    int d2 = __ldg(&c2[i]);
    float inv1 = 1.0f / (float)(d1 > 0 ? d1 : 1);
    float inv2 = 1.0f / (float)(d2 > 0 ? d2 : 1);
    float g1 = (d1 > 0) ? 1.0f : 0.0f;
    float g2 = (d2 > 0) ? 1.0f : 0.0f;
    float2 a1 = __ldg(&A1[i]);
    float2 a2 = __ldg(&A2[i]);
    float2 r;
    r.x = a1.x * inv1 + g1 * __ldg(&cvec[0]) + a2.x * inv2 + g2 * __ldg(&cvec[2]) + __ldg(&bc[0]);
    r.y = a1.y * inv1 + g1 * __ldg(&cvec[1]) + a2.y * inv2 + g2 * __ldg(&cvec[3]) + __ldg(&bc[1]);
    out[i] = r;
}

// ---------------- launch ----------------

static inline int cdiv(long long a, int b) { return (int)((a + b - 1) / b); }

static void build_csr(const int* dst, int* cnt, int* off, int* cur, int* bsum,
                      int* eidx, const int* src, int n, int e, cudaStream_t s)
{
    count_k<<<1184, 256, 0, s>>>(dst, cnt, e);
    int nb = cdiv(n, SCAN_B);
    scan_blocks_k<<<nb, SCAN_B, 0, s>>>(cnt, off, bsum, n);
    scan_sums_k<<<1, SCAN_B, 0, s>>>(bsum, nb);
    scan_add_k<<<nb, SCAN_B, 0, s>>>(off, bsum, n);
    fill_k<<<1184, 256, 0, s>>>(src, dst, off, cur, eidx, e);
}

extern "C" void kernel_launch(void* const* d_in, const int* in_sizes, int n_in,
                              void* d_out, int out_size)
{
    const float* features = (const float*)d_in[0];
    const float* W0 = (const float*)d_in[3];
    const float* b0 = (const float*)d_in[4];
    const float* W1 = (const float*)d_in[5];
    const float* b1 = (const float*)d_in[6];
    const float* Wc = (const float*)d_in[7];
    const float* bc = (const float*)d_in[8];
    const int* src_u2t = (const int*)d_in[9];
    const int* dst_u2t = (const int*)d_in[10];
    const int* src_t2u = (const int*)d_in[11];
    const int* dst_t2u = (const int*)d_in[12];
    const int* src_d2t = (const int*)d_in[13];
    const int* dst_d2t = (const int*)d_in[14];
    const int* src_t2d = (const int*)d_in[15];
    const int* dst_t2d = (const int*)d_in[16];

    const int nt = in_sizes[0] / D;
    const int nu = in_sizes[1] / D;
    const int nd = in_sizes[2] / D;
    const int e_u2t = in_sizes[9];
    const int e_t2u = in_sizes[11];
    const int e_d2t = in_sizes[13];
    const int e_t2d = in_sizes[15];

    __half2* feat_h;
    float *Wf, *cvec;
    float2 *z_u, *z_d, *acc_t1, *acc_t2;
    int *eidx_t2u, *eidx_t2d;
    int *cnt_u, *off_u, *cur_u, *cnt_d, *off_d, *cur_d;
    int *cnt_t1, *cnt_t2, *bsum;
    cudaGetSymbolAddress((void**)&feat_h, g_feat_h);
    cudaGetSymbolAddress((void**)&z_u, g_z_u);
    cudaGetSymbolAddress((void**)&z_d, g_z_d);
    cudaGetSymbolAddress((void**)&acc_t1, g_acc_t1);
    cudaGetSymbolAddress((void**)&acc_t2, g_acc_t2);
    cudaGetSymbolAddress((void**)&eidx_t2u, g_eidx_t2u);
    cudaGetSymbolAddress((void**)&eidx_t2d, g_eidx_t2d);
    cudaGetSymbolAddress((void**)&cnt_u, g_cnt_u);
    cudaGetSymbolAddress((void**)&off_u, g_off_u);
    cudaGetSymbolAddress((void**)&cur_u, g_cur_u);
    cudaGetSymbolAddress((void**)&cnt_d, g_cnt_d);
    cudaGetSymbolAddress((void**)&off_d, g_off_d);
    cudaGetSymbolAddress((void**)&cur_d, g_cur_d);
    cudaGetSymbolAddress((void**)&cnt_t1, g_cnt_t1);
    cudaGetSymbolAddress((void**)&cnt_t2, g_cnt_t2);
    cudaGetSymbolAddress((void**)&bsum, g_bsum);
    cudaGetSymbolAddress((void**)&Wf, g_Wf);
    cudaGetSymbolAddress((void**)&cvec, g_cvec);

    cudaStream_t s = 0;

    // zero counts/cursors/accumulators
    cudaMemsetAsync(cnt_u, 0, (size_t)nu * sizeof(int), s);
    cudaMemsetAsync(cur_u, 0, (size_t)nu * sizeof(int), s);
    cudaMemsetAsync(cnt_d, 0, (size_t)nd * sizeof(int), s);
    cudaMemsetAsync(cur_d, 0, (size_t)nd * sizeof(int), s);
    cudaMemsetAsync(cnt_t1, 0, (size_t)nt * sizeof(int), s);
    cudaMemsetAsync(cnt_t2, 0, (size_t)nt * sizeof(int), s);
    cudaMemsetAsync(acc_t1, 0, (size_t)nt * sizeof(float2), s);
    cudaMemsetAsync(acc_t2, 0, (size_t)nt * sizeof(float2), s);

    // fp16 feature table + folded weights
    convert_half_k<<<1184, 256, 0, s>>>(features, feat_h, nt * D / 2);
    prep_k<<<1, 256, 0, s>>>(W1, b1, Wc, Wf, cvec);

    // CSR builds only for layer-0 relations
    build_csr(dst_t2u, cnt_u, off_u, cur_u, bsum, eidx_t2u, src_t2u, nu, e_t2u, s);
    build_csr(dst_t2d, cnt_d, off_d, cur_d, bsum, eidx_t2d, src_t2d, nd, e_t2d, s);

    // in-degree counts for target nodes (means + bias gating)
    count_k<<<1184, 256, 0, s>>>(dst_u2t, cnt_t1, e_u2t);
    count_k<<<1184, 256, 0, s>>>(dst_d2t, cnt_t2, e_d2t);

    // fused: gather fp16 feats + mean + project + lrelu + folded classifier -> z
    gather_proj_k<<<cdiv((long long)nu * 16, 256), 256, 0, s>>>(
        (const float2*)feat_h, off_u, cnt_u, eidx_t2u, W0 + 1 * D * D, b0 + 1 * D, Wf + 0,     z_u, nu);
    gather_proj_k<<<cdiv((long long)nd * 16, 256), 256, 0, s>>>(
        (const float2*)feat_h, off_d, cnt_d, eidx_t2d, W0 + 3 * D * D, b0 + 3 * D, Wf + D * 2, z_d, nd);

    // layer-1 aggregation as tiny-payload atomic scatter
    scatter2_k<<<1184, 256, 0, s>>>(z_u, src_u2t, dst_u2t, acc_t1, e_u2t);
    scatter2_k<<<1184, 256, 0, s>>>(z_d, src_d2t, dst_d2t, acc_t2, e_d2t);

    // final combine
    combine_k<<<cdiv(nt, 256), 256, 0, s>>>(acc_t1, acc_t2, cnt_t1, cnt_t2, cvec, bc,
                                            (float2*)d_out, nt);
}